// round 1
// baseline (speedup 1.0000x reference)
#include <cuda_runtime.h>
#include <math.h>

#define Bn 8
#define Ln 2048
#define Cn 512
#define Hn 8
#define Dn 64
#define FFn 2048
#define BLn (Bn*Ln)          /* 16384 */
#define BHn (Bn*Hn)          /* 64    */
#define BHLn (BHn*Ln)        /* 131072*/
#define KVCHUNKS 8

// ---------------- scratch (static device globals; no allocation) ----------------
static __device__ float g_xbuf[BLn*Cn];
static __device__ float g_ln[BLn*Cn];
static __device__ float g_qk[BLn*2*Cn];      // also reused as conv output c [BLn,1024]
static __device__ float g_v[BLn*Cn];
static __device__ float g_q2[BHLn*Dn];
static __device__ float g_k2[BHLn*Dn];
static __device__ float g_kmean[BHn*Dn];
static __device__ float g_kv[BHn*Dn*Dn];
static __device__ float g_kvpart[KVCHUNKS*BHn*Dn*Dn];
static __device__ float g_z[BHLn];
static __device__ float g_spin[BLn*Cn];
static __device__ float g_h[BLn*Cn];
static __device__ float g_im2col[BLn*3*Cn];
static __device__ float g_wt[3*Cn*2*Cn];
static __device__ float g_ffn[(long)BLn*FFn];

// ---------------- small helpers ----------------
__device__ __forceinline__ float elu1(float x) {
    // elu(x)+1 : x>0 -> x+1 ; else exp(x)
    return x > 0.0f ? x + 1.0f : expf(x);
}

// ---------------- copy ----------------
__global__ void copy_kernel(const float* __restrict__ src, float* __restrict__ dst, int n4) {
    int i = blockIdx.x * blockDim.x + threadIdx.x;
    if (i < n4) ((float4*)dst)[i] = ((const float4*)src)[i];
}

// ---------------- LayerNorm: one block (128 thr) per row of 512 ----------------
__global__ void ln_kernel(const float* __restrict__ in, const float* __restrict__ gam,
                          const float* __restrict__ bet, float* __restrict__ out) {
    int row = blockIdx.x;
    int t = threadIdx.x;                 // 0..127
    const float4 v = ((const float4*)(in + (long)row * Cn))[t];
    float s  = v.x + v.y + v.z + v.w;
    float sq = v.x*v.x + v.y*v.y + v.z*v.z + v.w*v.w;
    #pragma unroll
    for (int o = 16; o; o >>= 1) {
        s  += __shfl_xor_sync(0xFFFFFFFFu, s,  o);
        sq += __shfl_xor_sync(0xFFFFFFFFu, sq, o);
    }
    __shared__ float ss[4], ssq[4];
    if ((t & 31) == 0) { ss[t >> 5] = s; ssq[t >> 5] = sq; }
    __syncthreads();
    s  = ss[0] + ss[1] + ss[2] + ss[3];
    sq = ssq[0] + ssq[1] + ssq[2] + ssq[3];
    float mu   = s * (1.0f / Cn);
    float var  = sq * (1.0f / Cn) - mu * mu;
    float rstd = rsqrtf(var + 1e-5f);
    float4 g4 = ((const float4*)gam)[t];
    float4 b4 = ((const float4*)bet)[t];
    float4 o4;
    o4.x = (v.x - mu) * rstd * g4.x + b4.x;
    o4.y = (v.y - mu) * rstd * g4.y + b4.y;
    o4.z = (v.z - mu) * rstd * g4.z + b4.z;
    o4.w = (v.w - mu) * rstd * g4.w + b4.w;
    ((float4*)(out + (long)row * Cn))[t] = o4;
}

// ---------------- qk post: elu+1 then LePE (raw-reshape depthwise conv) ----------------
// q[b,h,l,d] stored at g_qk[(b*Ln+l)*1024 + sel*512 + h*64 + d]  (sel 0=q, 1=k)
// lepe adds, at (l,d): sum_k w[d,k]*e(src(d*2048 + l + k - 1)) + b[d], src flat -> (idx>>6, idx&63)
__global__ void qk_post_kernel(const float* __restrict__ qk,
                               const float* __restrict__ lw, const float* __restrict__ lb,
                               float* __restrict__ q2, float* __restrict__ k2) {
    int idx = blockIdx.x * blockDim.x + threadIdx.x;          // over BHLn*Dn = 2^23
    int d  = idx & 63;
    int l  = (idx >> 6) & (Ln - 1);
    int bh = idx >> 17;
    int b = bh >> 3, h = bh & 7;
    long base = (long)b * Ln * 1024 + h * 64;
    float w0 = lw[d*3+0], w1 = lw[d*3+1], w2 = lw[d*3+2], bias = lb[d];
    int flat = d * Ln + l;
    #pragma unroll
    for (int sel = 0; sel < 2; sel++) {
        const float* src = qk + base + sel * 512;
        float acc = elu1(src[(long)l * 1024 + d]) + bias;     // identity + conv bias
        if (l - 1 >= 0) {
            int fi = flat - 1; acc += w0 * elu1(src[(long)(fi >> 6) * 1024 + (fi & 63)]);
        }
        {
            int fi = flat;     acc += w1 * elu1(src[(long)(fi >> 6) * 1024 + (fi & 63)]);
        }
        if (l + 1 < Ln) {
            int fi = flat + 1; acc += w2 * elu1(src[(long)(fi >> 6) * 1024 + (fi & 63)]);
        }
        (sel ? k2 : q2)[idx] = acc;
    }
}

// ---------------- k mean over L: one block per (b,h) ----------------
__global__ void kmean_kernel(const float* __restrict__ k2, float* __restrict__ km) {
    int bh = blockIdx.x;
    int t = threadIdx.x;          // 256
    int d = t & 63, part = t >> 6;
    float s = 0.0f;
    const float* base = k2 + (long)bh * Ln * Dn;
    for (int l = part; l < Ln; l += 4) s += base[l * 64 + d];
    __shared__ float sm[4][64];
    sm[part][d] = s;
    __syncthreads();
    if (part == 0)
        km[bh * 64 + d] = (sm[0][d] + sm[1][d] + sm[2][d] + sm[3][d]) * (1.0f / Ln);
}

// ---------------- z = 1/(q . kmean + 1e-6): one warp per row ----------------
__global__ void z_kernel(const float* __restrict__ q2, const float* __restrict__ km,
                         float* __restrict__ z) {
    int row  = blockIdx.x * 8 + (threadIdx.x >> 5);   // BHLn rows
    int lane = threadIdx.x & 31;
    int bh = row >> 11;
    float a = q2[(long)row * 64 + lane]      * km[bh * 64 + lane]
            + q2[(long)row * 64 + 32 + lane] * km[bh * 64 + 32 + lane];
    #pragma unroll
    for (int o = 16; o; o >>= 1) a += __shfl_xor_sync(0xFFFFFFFFu, a, o);
    if (lane == 0) z[row] = 1.0f / (a + 1e-6f);
}

// ---------------- kv partials: grid (BH, chunks), 64x64 output, K = Ln/chunks ----------------
__global__ void kv_kernel(const float* __restrict__ k2, const float* __restrict__ v,
                          float* __restrict__ part) {
    int bh = blockIdx.x, chunk = blockIdx.y;
    int b = bh >> 3, h = bh & 7;
    __shared__ float ks[32][64];
    __shared__ float vs[32][64];
    int t = threadIdx.x;                   // 256
    int e0 = (t & 15) * 4, d0 = (t >> 4) * 4;
    float acc[4][4] = {};
    int lc = Ln / KVCHUNKS;                // 256
    for (int l0 = chunk * lc; l0 < chunk * lc + lc; l0 += 32) {
        #pragma unroll
        for (int i = 0; i < 2; i++) {
            int idx = t + i * 256;         // 0..511
            int r = idx >> 4, c4 = (idx & 15) * 4;
            int l = l0 + r;
            *(float4*)&ks[r][c4] = *(const float4*)&k2[((long)bh * Ln + l) * 64 + c4];
            *(float4*)&vs[r][c4] = *(const float4*)&v[((long)(b * Ln + l)) * Cn + h * 64 + c4];
        }
        __syncthreads();
        #pragma unroll
        for (int l = 0; l < 32; l++) {
            float4 kr = *(const float4*)&ks[l][d0];
            float4 vr = *(const float4*)&vs[l][e0];
            float k_[4] = {kr.x, kr.y, kr.z, kr.w};
            float v_[4] = {vr.x, vr.y, vr.z, vr.w};
            #pragma unroll
            for (int i = 0; i < 4; i++)
                #pragma unroll
                for (int j = 0; j < 4; j++)
                    acc[i][j] += k_[i] * v_[j];
        }
        __syncthreads();
    }
    float* dst = part + ((long)chunk * BHn + bh) * (Dn * Dn);
    #pragma unroll
    for (int i = 0; i < 4; i++)
        #pragma unroll
        for (int j = 0; j < 4; j++)
            dst[(d0 + i) * 64 + e0 + j] = acc[i][j];
}

__global__ void kv_reduce_kernel(const float* __restrict__ part, float* __restrict__ kv) {
    int i = blockIdx.x * blockDim.x + threadIdx.x;    // BHn*Dn*Dn = 262144
    float s = 0.0f;
    #pragma unroll
    for (int c = 0; c < KVCHUNKS; c++) s += part[(long)c * (BHn * Dn * Dn) + i];
    kv[i] = s * (1.0f / Ln);
}

// ---------------- attention output, added in-place into xbuf ----------------
// grid (BH, Ln/32), block 256: 16 rows x (16 threads * 4 e) per iteration, 2 iters
__global__ void attn_out_kernel(const float* __restrict__ q2, const float* __restrict__ kv,
                                const float* __restrict__ z, float* __restrict__ xbuf) {
    int bh = blockIdx.x, b = bh >> 3, h = bh & 7;
    int lbase = blockIdx.y * 32;
    __shared__ float kvs[64][64];
    __shared__ float qs[16][64];
    int t = threadIdx.x;
    #pragma unroll
    for (int i = 0; i < 4; i++) {
        int idx = t + i * 256;             // 0..1023 float4s
        ((float4*)kvs)[idx] = ((const float4*)(kv + (long)bh * 4096))[idx];
    }
    int g = t >> 4;
    int e0 = (t & 15) * 4;
    for (int it = 0; it < 2; it++) {
        __syncthreads();
        int rbase = lbase + it * 16;
        #pragma unroll
        for (int i = 0; i < 4; i++) {
            int idx = t + i * 256;         // 0..1023
            int r = idx >> 6, c = idx & 63;
            qs[r][c] = q2[((long)bh * Ln + rbase + r) * 64 + c];
        }
        __syncthreads();
        int l = rbase + g;
        float4 acc = {0.f, 0.f, 0.f, 0.f};
        #pragma unroll
        for (int d = 0; d < 64; d++) {
            float qd = qs[g][d];
            float4 kvv = *(const float4*)&kvs[d][e0];
            acc.x += qd * kvv.x; acc.y += qd * kvv.y;
            acc.z += qd * kvv.z; acc.w += qd * kvv.w;
        }
        float zz = z[(long)bh * Ln + l];
        float* dst = &xbuf[((long)(b * Ln + l)) * Cn + h * 64 + e0];
        float4 cur = *(float4*)dst;
        cur.x += acc.x * zz; cur.y += acc.y * zz;
        cur.z += acc.z * zz; cur.w += acc.w * zz;
        *(float4*)dst = cur;
    }
}

// ---------------- conv weight transpose: wt[k][ci][co] = w[co][ci][k] ----------------
__global__ void wt_kernel(const float* __restrict__ w, float* __restrict__ wt) {
    int idx = blockIdx.x * blockDim.x + threadIdx.x;   // 3*512*1024
    if (idx >= 3 * Cn * 2 * Cn) return;
    int co = idx & 1023;
    int ci = (idx >> 10) & 511;
    int k  = idx >> 19;
    wt[idx] = w[co * 1536 + ci * 3 + k];
}

// ---------------- im2col for conv1d (kernel 3, pad 1, per-batch) ----------------
__global__ void im2col_kernel(const float* __restrict__ h, float* __restrict__ im) {
    long idx = (long)blockIdx.x * blockDim.x + threadIdx.x;  // BLn*384 float4 slots
    int col4 = (int)(idx % 384);
    long row = idx / 384;
    int k   = col4 / 128;
    int ci4 = col4 % 128;
    int ll = (int)(row & (Ln - 1));
    int j = ll + k - 1;
    float4 vv = {0.f, 0.f, 0.f, 0.f};
    if (j >= 0 && j < Ln) vv = ((const float4*)(h + (row + k - 1) * Cn))[ci4];
    ((float4*)(im + row * (3 * Cn)))[col4] = vv;
}

// ---------------- gate: xbuf += spin + vv*sigmoid(gg) ----------------
__global__ void gate_kernel(const float* __restrict__ c, const float* __restrict__ spin,
                            float* __restrict__ xbuf) {
    long idx = (long)blockIdx.x * blockDim.x + threadIdx.x;  // BLn*128 float4 slots
    int c4 = (int)(idx & 127);
    long row = idx >> 7;
    float4 vv = ((const float4*)(c + row * 1024))[c4];
    float4 gg = ((const float4*)(c + row * 1024 + 512))[c4];
    float4 sp = ((const float4*)(spin + row * Cn))[c4];
    float4 x  = ((float4*)(xbuf + row * Cn))[c4];
    x.x += sp.x + vv.x / (1.0f + expf(-gg.x));
    x.y += sp.y + vv.y / (1.0f + expf(-gg.y));
    x.z += sp.z + vv.z / (1.0f + expf(-gg.z));
    x.w += sp.w + vv.w / (1.0f + expf(-gg.w));
    ((float4*)(xbuf + row * Cn))[c4] = x;
}

// ---------------- SGEMM: C[M,N] = A[M,K] @ B[K,N] + bias (+gelu) (+res) ----------------
// 128x128x16 tile, 256 threads, 8x8 register tile, double-buffered smem.
// M%128==0, N%128==0, K%16==0 (all true for our shapes).
template<int EPI>
__global__ void __launch_bounds__(256, 2)
sgemm_kernel(const float* __restrict__ A, const float* __restrict__ Bm,
             const float* __restrict__ bias, const float* __restrict__ res,
             float* __restrict__ C, int M, int N, int K) {
    __shared__ float As[2][16][128];
    __shared__ float Bs[2][16][128];
    int t = threadIdx.x;
    int bm = blockIdx.y * 128, bn = blockIdx.x * 128;

    int arow = t >> 2;            // 0..63 (second half +64)
    int ac4  = (t & 3) * 4;
    int brow = t >> 5;            // 0..7 (second half +8)
    int bc4  = (t & 31) * 4;

    const float* Ag = A + (long)(bm + arow) * K + ac4;
    const float* Bg = Bm + (long)brow * N + bn + bc4;

    float4 pa0 = *(const float4*)Ag;
    float4 pa1 = *(const float4*)(Ag + (long)64 * K);
    float4 pb0 = *(const float4*)Bg;
    float4 pb1 = *(const float4*)(Bg + (long)8 * N);

    As[0][ac4 + 0][arow] = pa0.x; As[0][ac4 + 1][arow] = pa0.y;
    As[0][ac4 + 2][arow] = pa0.z; As[0][ac4 + 3][arow] = pa0.w;
    As[0][ac4 + 0][arow + 64] = pa1.x; As[0][ac4 + 1][arow + 64] = pa1.y;
    As[0][ac4 + 2][arow + 64] = pa1.z; As[0][ac4 + 3][arow + 64] = pa1.w;
    *(float4*)&Bs[0][brow][bc4]     = pb0;
    *(float4*)&Bs[0][brow + 8][bc4] = pb1;
    __syncthreads();

    int ty = t >> 4, tx = t & 15;
    float acc[8][8] = {};
    int nk = K >> 4;
    for (int kt = 0; kt < nk; kt++) {
        int cur = kt & 1, nxt = cur ^ 1;
        if (kt + 1 < nk) {
            const float* Ag2 = Ag + (kt + 1) * 16;
            const float* Bg2 = Bg + (long)(kt + 1) * 16 * N;
            pa0 = *(const float4*)Ag2;
            pa1 = *(const float4*)(Ag2 + (long)64 * K);
            pb0 = *(const float4*)Bg2;
            pb1 = *(const float4*)(Bg2 + (long)8 * N);
        }
        #pragma unroll
        for (int kk = 0; kk < 16; kk++) {
            float a[8], b[8];
            *(float4*)&a[0] = *(const float4*)&As[cur][kk][ty * 8];
            *(float4*)&a[4] = *(const float4*)&As[cur][kk][ty * 8 + 4];
            *(float4*)&b[0] = *(const float4*)&Bs[cur][kk][tx * 8];
            *(float4*)&b[4] = *(const float4*)&Bs[cur][kk][tx * 8 + 4];
            #pragma unroll
            for (int i = 0; i < 8; i++)
                #pragma unroll
                for (int j = 0; j < 8; j++)
                    acc[i][j] += a[i] * b[j];
        }
        if (kt + 1 < nk) {
            As[nxt][ac4 + 0][arow] = pa0.x; As[nxt][ac4 + 1][arow] = pa0.y;
            As[nxt][ac4 + 2][arow] = pa0.z; As[nxt][ac4 + 3][arow] = pa0.w;
            As[nxt][ac4 + 0][arow + 64] = pa1.x; As[nxt][ac4 + 1][arow + 64] = pa1.y;
            As[nxt][ac4 + 2][arow + 64] = pa1.z; As[nxt][ac4 + 3][arow + 64] = pa1.w;
            *(float4*)&Bs[nxt][brow][bc4]     = pb0;
            *(float4*)&Bs[nxt][brow + 8][bc4] = pb1;
            __syncthreads();
        }
    }

    int crow = bm + ty * 8, ccol = bn + tx * 8;
    #pragma unroll
    for (int i = 0; i < 8; i++) {
        float out[8];
        float* cp = C + (long)(crow + i) * N + ccol;
        #pragma unroll
        for (int j = 0; j < 8; j++) {
            float v = acc[i][j] + bias[ccol + j];
            if (EPI == 1) v = 0.5f * v * (1.0f + erff(v * 0.70710678118654752f));
            out[j] = v;
        }
        if (res) {
            const float* rp = res + (long)(crow + i) * N + ccol;
            #pragma unroll
            for (int j = 0; j < 8; j++) out[j] += rp[j];
        }
        *(float4*)cp       = *(float4*)&out[0];
        *(float4*)(cp + 4) = *(float4*)&out[4];
    }
}

// ---------------- host launcher ----------------
extern "C" void kernel_launch(void* const* d_in, const int* in_sizes, int n_in,
                              void* d_out, int out_size) {
    const float* x      = (const float*)d_in[0];
    const float* g1     = (const float*)d_in[1];
    const float* b1     = (const float*)d_in[2];
    const float* qk_w   = (const float*)d_in[3];
    const float* qk_b   = (const float*)d_in[4];
    const float* v_w    = (const float*)d_in[5];
    const float* v_b    = (const float*)d_in[6];
    const float* lepe_w = (const float*)d_in[7];
    const float* lepe_b = (const float*)d_in[8];
    const float* g2     = (const float*)d_in[9];
    const float* b2     = (const float*)d_in[10];
    const float* spn_g  = (const float*)d_in[11];
    const float* spn_b  = (const float*)d_in[12];
    const float* sp_cw  = (const float*)d_in[13];
    const float* sp_cb  = (const float*)d_in[14];
    const float* g3     = (const float*)d_in[15];
    const float* b3     = (const float*)d_in[16];
    const float* w1     = (const float*)d_in[17];
    const float* bb1    = (const float*)d_in[18];
    const float* w2     = (const float*)d_in[19];
    const float* bb2    = (const float*)d_in[20];
    float* out = (float*)d_out;

    float *xbuf, *ln, *qk, *v, *q2, *k2, *km, *kv, *kvpart, *z, *spin, *hb, *im, *wt, *ffn;
    cudaGetSymbolAddress((void**)&xbuf,   g_xbuf);
    cudaGetSymbolAddress((void**)&ln,     g_ln);
    cudaGetSymbolAddress((void**)&qk,     g_qk);
    cudaGetSymbolAddress((void**)&v,      g_v);
    cudaGetSymbolAddress((void**)&q2,     g_q2);
    cudaGetSymbolAddress((void**)&k2,     g_k2);
    cudaGetSymbolAddress((void**)&km,     g_kmean);
    cudaGetSymbolAddress((void**)&kv,     g_kv);
    cudaGetSymbolAddress((void**)&kvpart, g_kvpart);
    cudaGetSymbolAddress((void**)&z,      g_z);
    cudaGetSymbolAddress((void**)&spin,   g_spin);
    cudaGetSymbolAddress((void**)&hb,     g_h);
    cudaGetSymbolAddress((void**)&im,     g_im2col);
    cudaGetSymbolAddress((void**)&wt,     g_wt);
    cudaGetSymbolAddress((void**)&ffn,    g_ffn);

    // Block 1: x = x + attn(LN1(x))
    copy_kernel<<<(BLn * Cn / 4) / 256, 256>>>(x, xbuf, BLn * Cn / 4);
    ln_kernel<<<BLn, 128>>>(xbuf, g1, b1, ln);
    sgemm_kernel<0><<<dim3(1024 / 128, BLn / 128), 256>>>(ln, qk_w, qk_b, nullptr, qk, BLn, 1024, Cn);
    sgemm_kernel<0><<<dim3(Cn / 128, BLn / 128), 256>>>(ln, v_w, v_b, nullptr, v, BLn, Cn, Cn);
    qk_post_kernel<<<(BHLn * Dn) / 256, 256>>>(qk, lepe_w, lepe_b, q2, k2);
    kmean_kernel<<<BHn, 256>>>(k2, km);
    z_kernel<<<BHLn / 8, 256>>>(q2, km, z);
    kv_kernel<<<dim3(BHn, KVCHUNKS), 256>>>(k2, v, kvpart);
    kv_reduce_kernel<<<(BHn * Dn * Dn) / 256, 256>>>(kvpart, kv);
    attn_out_kernel<<<dim3(BHn, Ln / 32), 256>>>(q2, kv, z, xbuf);

    // Block 2: gated conv state path
    ln_kernel<<<BLn, 128>>>(xbuf, g2, b2, spin);
    ln_kernel<<<BLn, 128>>>(spin, spn_g, spn_b, hb);
    wt_kernel<<<(3 * Cn * 2 * Cn) / 256, 256>>>(sp_cw, wt);
    im2col_kernel<<<(BLn * 384) / 256, 256>>>(hb, im);
    sgemm_kernel<0><<<dim3(1024 / 128, BLn / 128), 256>>>(im, wt, sp_cb, nullptr, qk, BLn, 1024, 3 * Cn);
    gate_kernel<<<(BLn * 128) / 256, 256>>>(qk, spin, xbuf);

    // Block 3: FFN
    ln_kernel<<<BLn, 128>>>(xbuf, g3, b3, ln);
    sgemm_kernel<1><<<dim3(FFn / 128, BLn / 128), 256>>>(ln, w1, bb1, nullptr, ffn, BLn, FFn, Cn);
    sgemm_kernel<0><<<dim3(Cn / 128, BLn / 128), 256>>>(ffn, w2, bb2, xbuf, out, BLn, Cn, FFn);
}

// round 3
// speedup vs baseline: 2.2438x; 2.2438x over previous
#include <cuda_runtime.h>
#include <math.h>
#include <stdint.h>

#define Bn 8
#define Ln 2048
#define Cn 512
#define Hn 8
#define Dn 64
#define FFn 2048
#define BLn (Bn*Ln)          /* 16384 */
#define BHn (Bn*Hn)          /* 64    */
#define BHLn (BHn*Ln)        /* 131072*/
#define KVCHUNKS 8

// ---------------- scratch (static device globals; no allocation) ----------------
static __device__ __align__(16) float g_xbuf[BLn*Cn];
static __device__ __align__(16) float g_ln[BLn*Cn];
static __device__ __align__(16) float g_qk[BLn*2*Cn];      // also reused as conv output c [BLn,1024]
static __device__ __align__(16) float g_v[BLn*Cn];
static __device__ __align__(16) float g_q2[BHLn*Dn];
static __device__ __align__(16) float g_k2[BHLn*Dn];
static __device__ __align__(16) float g_kmean[BHn*Dn];
static __device__ __align__(16) float g_kv[BHn*Dn*Dn];
static __device__ __align__(16) float g_kvpart[KVCHUNKS*BHn*Dn*Dn];
static __device__ __align__(16) float g_z[BHLn];
static __device__ __align__(16) float g_spin[BLn*Cn];
static __device__ __align__(16) float g_h[BLn*Cn];
static __device__ __align__(16) float g_im2col[BLn*3*Cn];
static __device__ __align__(16) float g_ffn[(long)BLn*FFn];
// transposed (N-major) weights for tensor-core GEMM (B^T, [N,K] row-major)
static __device__ __align__(16) float g_qkT[1024*512];
static __device__ __align__(16) float g_vT[512*512];
static __device__ __align__(16) float g_w1T[2048*512];
static __device__ __align__(16) float g_w2T[512*2048];
static __device__ __align__(16) float g_wtT[1024*1536];

// ---------------- PTX helpers ----------------
__device__ __forceinline__ uint32_t smem_u32(const void* p) {
    uint32_t a;
    asm("{ .reg .u64 t; cvta.to.shared.u64 t, %1; cvt.u32.u64 %0, t; }" : "=r"(a) : "l"(p));
    return a;
}
__device__ __forceinline__ float rnd_tf32(float x) {
    float r; asm("cvt.rna.tf32.f32 %0, %1;" : "=f"(r) : "f"(x)); return r;
}
__device__ __forceinline__ void cpasync16(uint32_t saddr, const void* g) {
    asm volatile("cp.async.cg.shared.global [%0], [%1], 16;" :: "r"(saddr), "l"(g) : "memory");
}
#define CP_COMMIT() asm volatile("cp.async.commit_group;" ::: "memory")
#define CP_WAIT1()  asm volatile("cp.async.wait_group 1;" ::: "memory")

// tf32 warp mma: D(16x8) += A(16x8) * B(8x8);  a: 4 regs, b: 2 regs, c: 4 f32
__device__ __forceinline__ void mma_tf32(float* c, const uint32_t* a, const uint32_t* b) {
    asm volatile(
        "mma.sync.aligned.m16n8k8.row.col.f32.tf32.tf32.f32 "
        "{%0,%1,%2,%3}, {%4,%5,%6,%7}, {%8,%9}, {%0,%1,%2,%3};"
        : "+f"(c[0]), "+f"(c[1]), "+f"(c[2]), "+f"(c[3])
        : "r"(a[0]), "r"(a[1]), "r"(a[2]), "r"(a[3]), "r"(b[0]), "r"(b[1]));
}

// ---------------- small helpers ----------------
__device__ __forceinline__ float elu1(float x) { return x > 0.0f ? x + 1.0f : expf(x); }

// ---------------- copy ----------------
__global__ void copy_kernel(const float* __restrict__ src, float* __restrict__ dst, int n4) {
    int i = blockIdx.x * blockDim.x + threadIdx.x;
    if (i < n4) ((float4*)dst)[i] = ((const float4*)src)[i];
}

// ---------------- LayerNorm ----------------
template<bool RND>
__global__ void ln_kernel(const float* __restrict__ in, const float* __restrict__ gam,
                          const float* __restrict__ bet, float* __restrict__ out) {
    int row = blockIdx.x;
    int t = threadIdx.x;                 // 0..127
    const float4 v = ((const float4*)(in + (long)row * Cn))[t];
    float s  = v.x + v.y + v.z + v.w;
    float sq = v.x*v.x + v.y*v.y + v.z*v.z + v.w*v.w;
    #pragma unroll
    for (int o = 16; o; o >>= 1) {
        s  += __shfl_xor_sync(0xFFFFFFFFu, s,  o);
        sq += __shfl_xor_sync(0xFFFFFFFFu, sq, o);
    }
    __shared__ float ss[4], ssq[4];
    if ((t & 31) == 0) { ss[t >> 5] = s; ssq[t >> 5] = sq; }
    __syncthreads();
    s  = ss[0] + ss[1] + ss[2] + ss[3];
    sq = ssq[0] + ssq[1] + ssq[2] + ssq[3];
    float mu   = s * (1.0f / Cn);
    float var  = sq * (1.0f / Cn) - mu * mu;
    float rstd = rsqrtf(var + 1e-5f);
    float4 g4 = ((const float4*)gam)[t];
    float4 b4 = ((const float4*)bet)[t];
    float4 o4;
    o4.x = (v.x - mu) * rstd * g4.x + b4.x;
    o4.y = (v.y - mu) * rstd * g4.y + b4.y;
    o4.z = (v.z - mu) * rstd * g4.z + b4.z;
    o4.w = (v.w - mu) * rstd * g4.w + b4.w;
    if (RND) {
        o4.x = rnd_tf32(o4.x); o4.y = rnd_tf32(o4.y);
        o4.z = rnd_tf32(o4.z); o4.w = rnd_tf32(o4.w);
    }
    ((float4*)(out + (long)row * Cn))[t] = o4;
}

// ---------------- qk post: elu+1 then LePE ----------------
__global__ void qk_post_kernel(const float* __restrict__ qk,
                               const float* __restrict__ lw, const float* __restrict__ lb,
                               float* __restrict__ q2, float* __restrict__ k2) {
    int idx = blockIdx.x * blockDim.x + threadIdx.x;          // over BHLn*Dn
    int d  = idx & 63;
    int l  = (idx >> 6) & (Ln - 1);
    int bh = idx >> 17;
    int b = bh >> 3, h = bh & 7;
    long base = (long)b * Ln * 1024 + h * 64;
    float w0 = lw[d*3+0], w1 = lw[d*3+1], w2 = lw[d*3+2], bias = lb[d];
    int flat = d * Ln + l;
    #pragma unroll
    for (int sel = 0; sel < 2; sel++) {
        const float* src = qk + base + sel * 512;
        float acc = elu1(src[(long)l * 1024 + d]) + bias;
        if (l - 1 >= 0) {
            int fi = flat - 1; acc += w0 * elu1(src[(long)(fi >> 6) * 1024 + (fi & 63)]);
        }
        {
            int fi = flat;     acc += w1 * elu1(src[(long)(fi >> 6) * 1024 + (fi & 63)]);
        }
        if (l + 1 < Ln) {
            int fi = flat + 1; acc += w2 * elu1(src[(long)(fi >> 6) * 1024 + (fi & 63)]);
        }
        (sel ? k2 : q2)[idx] = acc;
    }
}

// ---------------- k mean ----------------
__global__ void kmean_kernel(const float* __restrict__ k2, float* __restrict__ km) {
    int bh = blockIdx.x;
    int t = threadIdx.x;
    int d = t & 63, part = t >> 6;
    float s = 0.0f;
    const float* base = k2 + (long)bh * Ln * Dn;
    for (int l = part; l < Ln; l += 4) s += base[l * 64 + d];
    __shared__ float sm[4][64];
    sm[part][d] = s;
    __syncthreads();
    if (part == 0)
        km[bh * 64 + d] = (sm[0][d] + sm[1][d] + sm[2][d] + sm[3][d]) * (1.0f / Ln);
}

// ---------------- z ----------------
__global__ void z_kernel(const float* __restrict__ q2, const float* __restrict__ km,
                         float* __restrict__ z) {
    int row  = blockIdx.x * 8 + (threadIdx.x >> 5);
    int lane = threadIdx.x & 31;
    int bh = row >> 11;
    float a = q2[(long)row * 64 + lane]      * km[bh * 64 + lane]
            + q2[(long)row * 64 + 32 + lane] * km[bh * 64 + 32 + lane];
    #pragma unroll
    for (int o = 16; o; o >>= 1) a += __shfl_xor_sync(0xFFFFFFFFu, a, o);
    if (lane == 0) z[row] = 1.0f / (a + 1e-6f);
}

// ---------------- kv partials ----------------
__global__ void kv_kernel(const float* __restrict__ k2, const float* __restrict__ v,
                          float* __restrict__ part) {
    int bh = blockIdx.x, chunk = blockIdx.y;
    int b = bh >> 3, h = bh & 7;
    __shared__ float ks[32][64];
    __shared__ float vs[32][64];
    int t = threadIdx.x;
    int e0 = (t & 15) * 4, d0 = (t >> 4) * 4;
    float acc[4][4] = {};
    int lc = Ln / KVCHUNKS;
    for (int l0 = chunk * lc; l0 < chunk * lc + lc; l0 += 32) {
        #pragma unroll
        for (int i = 0; i < 2; i++) {
            int idx = t + i * 256;
            int r = idx >> 4, c4 = (idx & 15) * 4;
            int l = l0 + r;
            *(float4*)&ks[r][c4] = *(const float4*)&k2[((long)bh * Ln + l) * 64 + c4];
            *(float4*)&vs[r][c4] = *(const float4*)&v[((long)(b * Ln + l)) * Cn + h * 64 + c4];
        }
        __syncthreads();
        #pragma unroll
        for (int l = 0; l < 32; l++) {
            float4 kr = *(const float4*)&ks[l][d0];
            float4 vr = *(const float4*)&vs[l][e0];
            float k_[4] = {kr.x, kr.y, kr.z, kr.w};
            float v_[4] = {vr.x, vr.y, vr.z, vr.w};
            #pragma unroll
            for (int i = 0; i < 4; i++)
                #pragma unroll
                for (int j = 0; j < 4; j++)
                    acc[i][j] += k_[i] * v_[j];
        }
        __syncthreads();
    }
    float* dst = part + ((long)chunk * BHn + bh) * (Dn * Dn);
    #pragma unroll
    for (int i = 0; i < 4; i++)
        #pragma unroll
        for (int j = 0; j < 4; j++)
            dst[(d0 + i) * 64 + e0 + j] = acc[i][j];
}

__global__ void kv_reduce_kernel(const float* __restrict__ part, float* __restrict__ kv) {
    int i = blockIdx.x * blockDim.x + threadIdx.x;
    float s = 0.0f;
    #pragma unroll
    for (int c = 0; c < KVCHUNKS; c++) s += part[(long)c * (BHn * Dn * Dn) + i];
    kv[i] = s * (1.0f / Ln);
}

// ---------------- attention output ----------------
__global__ void attn_out_kernel(const float* __restrict__ q2, const float* __restrict__ kv,
                                const float* __restrict__ z, float* __restrict__ xbuf) {
    int bh = blockIdx.x, b = bh >> 3, h = bh & 7;
    int lbase = blockIdx.y * 32;
    __shared__ float kvs[64][64];
    __shared__ float qs[16][64];
    int t = threadIdx.x;
    #pragma unroll
    for (int i = 0; i < 4; i++) {
        int idx = t + i * 256;
        ((float4*)kvs)[idx] = ((const float4*)(kv + (long)bh * 4096))[idx];
    }
    int g = t >> 4;
    int e0 = (t & 15) * 4;
    for (int it = 0; it < 2; it++) {
        __syncthreads();
        int rbase = lbase + it * 16;
        #pragma unroll
        for (int i = 0; i < 4; i++) {
            int idx = t + i * 256;
            int r = idx >> 6, c = idx & 63;
            qs[r][c] = q2[((long)bh * Ln + rbase + r) * 64 + c];
        }
        __syncthreads();
        int l = rbase + g;
        float4 acc = {0.f, 0.f, 0.f, 0.f};
        #pragma unroll
        for (int d = 0; d < 64; d++) {
            float qd = qs[g][d];
            float4 kvv = *(const float4*)&kvs[d][e0];
            acc.x += qd * kvv.x; acc.y += qd * kvv.y;
            acc.z += qd * kvv.z; acc.w += qd * kvv.w;
        }
        float zz = z[(long)bh * Ln + l];
        float* dst = &xbuf[((long)(b * Ln + l)) * Cn + h * 64 + e0];
        float4 cur = *(float4*)dst;
        cur.x += acc.x * zz; cur.y += acc.y * zz;
        cur.z += acc.z * zz; cur.w += acc.w * zz;
        *(float4*)dst = cur;
    }
}

// ---------------- weight transposes (B^T builders, with tf32 rounding) ----------------
__global__ void transpose_rnd_kernel(const float* __restrict__ src, float* __restrict__ dst,
                                     int K, int N) {
    long idx = (long)blockIdx.x * blockDim.x + threadIdx.x;
    if (idx >= (long)K * N) return;
    int k = (int)(idx % K);
    int n = (int)(idx / K);
    dst[idx] = rnd_tf32(src[(long)k * N + n]);
}

// conv weight: BT[co][kk=k*512+ci] = sp_cw[co*1536 + ci*3 + k]
__global__ void wtT_kernel(const float* __restrict__ w, float* __restrict__ wtT) {
    long idx = (long)blockIdx.x * blockDim.x + threadIdx.x;   // 1024*1536
    if (idx >= 1024L * 1536) return;
    int r  = (int)(idx % 1536);
    int co = (int)(idx / 1536);
    int k  = r >> 9;
    int ci = r & 511;
    wtT[idx] = rnd_tf32(w[co * 1536 + ci * 3 + k]);
}

// ---------------- im2col (rounds to tf32) ----------------
__global__ void im2col_kernel(const float* __restrict__ h, float* __restrict__ im) {
    long idx = (long)blockIdx.x * blockDim.x + threadIdx.x;
    int col4 = (int)(idx % 384);
    long row = idx / 384;
    int k   = col4 / 128;
    int ci4 = col4 % 128;
    int ll = (int)(row & (Ln - 1));
    int j = ll + k - 1;
    float4 vv = {0.f, 0.f, 0.f, 0.f};
    if (j >= 0 && j < Ln) {
        vv = ((const float4*)(h + (row + k - 1) * Cn))[ci4];
        vv.x = rnd_tf32(vv.x); vv.y = rnd_tf32(vv.y);
        vv.z = rnd_tf32(vv.z); vv.w = rnd_tf32(vv.w);
    }
    ((float4*)(im + row * (3 * Cn)))[col4] = vv;
}

// ---------------- gate ----------------
__global__ void gate_kernel(const float* __restrict__ c, const float* __restrict__ spin,
                            float* __restrict__ xbuf) {
    long idx = (long)blockIdx.x * blockDim.x + threadIdx.x;
    int c4 = (int)(idx & 127);
    long row = idx >> 7;
    float4 vv = ((const float4*)(c + row * 1024))[c4];
    float4 gg = ((const float4*)(c + row * 1024 + 512))[c4];
    float4 sp = ((const float4*)(spin + row * Cn))[c4];
    float4 x  = ((float4*)(xbuf + row * Cn))[c4];
    x.x += sp.x + vv.x / (1.0f + expf(-gg.x));
    x.y += sp.y + vv.y / (1.0f + expf(-gg.y));
    x.z += sp.z + vv.z / (1.0f + expf(-gg.z));
    x.w += sp.w + vv.w / (1.0f + expf(-gg.w));
    ((float4*)(xbuf + row * Cn))[c4] = x;
}

// ================= tf32 mma.sync GEMM =================
// C[M,N] = A[M,K] @ Bt[N,K]^T.  CTA tile 128x128, K-chunk 16, 3-stage cp.async.
// 8 warps: warp grid 2(m) x 4(n), warp tile 64x32 = 4x4 m16n8k8 atoms.
// smem per stage: A 8KB + B 8KB.  Layout: [kb][row][kk^(row&4)] floats (kb = k/8).
// EPI: 0 = bias; 1 = bias + exact GELU + tf32 round; 2 = bias + residual add.
#define GSM (3 * 16384)

template<int EPI>
__global__ void __launch_bounds__(256, 2)
gemm_mma(const float* __restrict__ A, const float* __restrict__ Bt,
         const float* __restrict__ bias, const float* __restrict__ res,
         float* __restrict__ C, int M, int N, int K) {
    extern __shared__ float sm[];
    uint32_t sb = smem_u32(sm);
    int t = threadIdx.x, wid = t >> 5, lane = t & 31;
    int g = lane >> 2, tig = lane & 3;
    int bm = blockIdx.y * 128, bn = blockIdx.x * 128;
    int wm = (wid >> 2) * 64, wn = (wid & 3) * 32;

    // ---- per-thread load slots: 2 float4 for A, 2 for B per stage ----
    const float* aG[2]; const float* bG[2]; uint32_t offA[2], offB[2];
    #pragma unroll
    for (int i = 0; i < 2; i++) {
        int idx = t + i * 256;                 // 0..511
        int m  = idx >> 2;                     // 0..127
        int k4 = idx & 3;                      // float4 index in K-chunk
        int kb = k4 >> 1;
        int kkb = (k4 & 1) * 4;
        uint32_t phys = (uint32_t)(kkb ^ (m & 4));
        uint32_t off = ((uint32_t)(kb * 128 + m) * 8 + phys) * 4;
        offA[i] = off;
        offB[i] = off + 8192;
        aG[i] = A + (long)(bm + m) * K + k4 * 4;
        bG[i] = Bt + (long)(bn + m) * K + k4 * 4;
    }

    int nk = K >> 4;   // K-chunks of 16

    // prologue: stages 0,1
    #pragma unroll
    for (int s = 0; s < 2; s++) {
        uint32_t stb = sb + s * 16384;
        #pragma unroll
        for (int i = 0; i < 2; i++) {
            cpasync16(stb + offA[i], aG[i] + s * 16);
            cpasync16(stb + offB[i], bG[i] + s * 16);
        }
        CP_COMMIT();
    }
    CP_WAIT1();
    __syncthreads();

    float acc[4][4][4] = {};

    for (int kt = 0; kt < nk; kt++) {
        // issue loads for kt+2
        if (kt + 2 < nk) {
            uint32_t stb = sb + ((kt + 2) % 3) * 16384;
            #pragma unroll
            for (int i = 0; i < 2; i++) {
                cpasync16(stb + offA[i], aG[i] + (long)(kt + 2) * 16);
                cpasync16(stb + offB[i], bG[i] + (long)(kt + 2) * 16);
            }
        }
        CP_COMMIT();

        // compute stage kt%3
        const float* sA = sm + (kt % 3) * 4096;
        const float* sB = sA + 2048;
        #pragma unroll
        for (int kb = 0; kb < 2; kb++) {
            const float* bA = sA + kb * 1024;
            const float* bB = sB + kb * 1024;
            uint32_t a[4][4], b[4][2];
            #pragma unroll
            for (int mt = 0; mt < 4; mt++) {
                int m0 = wm + mt * 16 + g;
                int x  = m0 & 4;                   // (m0+8)&4 == m0&4
                a[mt][0] = __float_as_uint(bA[m0 * 8 +  (tig      ^ x)]);
                a[mt][1] = __float_as_uint(bA[(m0 + 8) * 8 + (tig ^ x)]);
                a[mt][2] = __float_as_uint(bA[m0 * 8 + ((tig + 4) ^ x)]);
                a[mt][3] = __float_as_uint(bA[(m0 + 8) * 8 + ((tig + 4) ^ x)]);
            }
            #pragma unroll
            for (int nt = 0; nt < 4; nt++) {
                int n0 = wn + nt * 8 + g;
                int x  = n0 & 4;
                b[nt][0] = __float_as_uint(bB[n0 * 8 +  (tig      ^ x)]);
                b[nt][1] = __float_as_uint(bB[n0 * 8 + ((tig + 4) ^ x)]);
            }
            #pragma unroll
            for (int mt = 0; mt < 4; mt++)
                #pragma unroll
                for (int nt = 0; nt < 4; nt++)
                    mma_tf32(acc[mt][nt], a[mt], b[nt]);
        }

        CP_WAIT1();
        __syncthreads();
    }

    // ---- epilogue ----
    #pragma unroll
    for (int mt = 0; mt < 4; mt++) {
        int row = bm + wm + mt * 16 + g;
        #pragma unroll
        for (int nt = 0; nt < 4; nt++) {
            int col = bn + wn + nt * 8 + tig * 2;
            float b0 = bias[col], b1 = bias[col + 1];
            float v00 = acc[mt][nt][0] + b0;
            float v01 = acc[mt][nt][1] + b1;
            float v10 = acc[mt][nt][2] + b0;
            float v11 = acc[mt][nt][3] + b1;
            if (EPI == 1) {
                v00 = rnd_tf32(0.5f * v00 * (1.0f + erff(v00 * 0.70710678118654752f)));
                v01 = rnd_tf32(0.5f * v01 * (1.0f + erff(v01 * 0.70710678118654752f)));
                v10 = rnd_tf32(0.5f * v10 * (1.0f + erff(v10 * 0.70710678118654752f)));
                v11 = rnd_tf32(0.5f * v11 * (1.0f + erff(v11 * 0.70710678118654752f)));
            }
            if (EPI == 2) {
                const float* r0 = res + (long)row * N + col;
                const float* r1 = res + (long)(row + 8) * N + col;
                v00 += r0[0]; v01 += r0[1];
                v10 += r1[0]; v11 += r1[1];
            }
            float2 p0 = {v00, v01}, p1 = {v10, v11};
            *(float2*)(C + (long)row * N + col)       = p0;
            *(float2*)(C + (long)(row + 8) * N + col) = p1;
        }
    }
}

// ---------------- host launcher ----------------
extern "C" void kernel_launch(void* const* d_in, const int* in_sizes, int n_in,
                              void* d_out, int out_size) {
    const float* x      = (const float*)d_in[0];
    const float* g1     = (const float*)d_in[1];
    const float* b1     = (const float*)d_in[2];
    const float* qk_w   = (const float*)d_in[3];
    const float* qk_b   = (const float*)d_in[4];
    const float* v_w    = (const float*)d_in[5];
    const float* v_b    = (const float*)d_in[6];
    const float* lepe_w = (const float*)d_in[7];
    const float* lepe_b = (const float*)d_in[8];
    const float* g2     = (const float*)d_in[9];
    const float* b2     = (const float*)d_in[10];
    const float* spn_g  = (const float*)d_in[11];
    const float* spn_b  = (const float*)d_in[12];
    const float* sp_cw  = (const float*)d_in[13];
    const float* sp_cb  = (const float*)d_in[14];
    const float* g3     = (const float*)d_in[15];
    const float* b3     = (const float*)d_in[16];
    const float* w1     = (const float*)d_in[17];
    const float* bb1    = (const float*)d_in[18];
    const float* w2     = (const float*)d_in[19];
    const float* bb2    = (const float*)d_in[20];
    float* out = (float*)d_out;

    float *xbuf, *ln, *qk, *v, *q2, *k2, *km, *kv, *kvpart, *z, *spin, *hb, *im, *ffn;
    float *qkT, *vT, *w1T, *w2T, *wtT;
    cudaGetSymbolAddress((void**)&xbuf,   g_xbuf);
    cudaGetSymbolAddress((void**)&ln,     g_ln);
    cudaGetSymbolAddress((void**)&qk,     g_qk);
    cudaGetSymbolAddress((void**)&v,      g_v);
    cudaGetSymbolAddress((void**)&q2,     g_q2);
    cudaGetSymbolAddress((void**)&k2,     g_k2);
    cudaGetSymbolAddress((void**)&km,     g_kmean);
    cudaGetSymbolAddress((void**)&kv,     g_kv);
    cudaGetSymbolAddress((void**)&kvpart, g_kvpart);
    cudaGetSymbolAddress((void**)&z,      g_z);
    cudaGetSymbolAddress((void**)&spin,   g_spin);
    cudaGetSymbolAddress((void**)&hb,     g_h);
    cudaGetSymbolAddress((void**)&im,     g_im2col);
    cudaGetSymbolAddress((void**)&ffn,    g_ffn);
    cudaGetSymbolAddress((void**)&qkT,    g_qkT);
    cudaGetSymbolAddress((void**)&vT,     g_vT);
    cudaGetSymbolAddress((void**)&w1T,    g_w1T);
    cudaGetSymbolAddress((void**)&w2T,    g_w2T);
    cudaGetSymbolAddress((void**)&wtT,    g_wtT);

    cudaFuncSetAttribute(gemm_mma<0>, cudaFuncAttributeMaxDynamicSharedMemorySize, GSM);
    cudaFuncSetAttribute(gemm_mma<1>, cudaFuncAttributeMaxDynamicSharedMemorySize, GSM);
    cudaFuncSetAttribute(gemm_mma<2>, cudaFuncAttributeMaxDynamicSharedMemorySize, GSM);

    // weight transposes (B^T, tf32-rounded)
    transpose_rnd_kernel<<<(512 * 1024 + 255) / 256, 256>>>(qk_w, qkT, 512, 1024);
    transpose_rnd_kernel<<<(512 * 512 + 255) / 256, 256>>>(v_w, vT, 512, 512);
    transpose_rnd_kernel<<<(512 * 2048 + 255) / 256, 256>>>(w1, w1T, 512, 2048);
    transpose_rnd_kernel<<<(2048 * 512 + 255) / 256, 256>>>(w2, w2T, 2048, 512);
    wtT_kernel<<<(1024 * 1536 + 255) / 256, 256>>>(sp_cw, wtT);

    // Block 1: x = x + attn(LN1(x))
    copy_kernel<<<(BLn * Cn / 4) / 256, 256>>>(x, xbuf, BLn * Cn / 4);
    ln_kernel<true><<<BLn, 128>>>(xbuf, g1, b1, ln);
    gemm_mma<0><<<dim3(1024 / 128, BLn / 128), 256, GSM>>>(ln, qkT, qk_b, nullptr, qk, BLn, 1024, Cn);
    gemm_mma<0><<<dim3(512 / 128, BLn / 128), 256, GSM>>>(ln, vT, v_b, nullptr, v, BLn, 512, Cn);
    qk_post_kernel<<<(BHLn * Dn) / 256, 256>>>(qk, lepe_w, lepe_b, q2, k2);
    kmean_kernel<<<BHn, 256>>>(k2, km);
    z_kernel<<<BHLn / 8, 256>>>(q2, km, z);
    kv_kernel<<<dim3(BHn, KVCHUNKS), 256>>>(k2, v, kvpart);
    kv_reduce_kernel<<<(BHn * Dn * Dn) / 256, 256>>>(kvpart, kv);
    attn_out_kernel<<<dim3(BHn, Ln / 32), 256>>>(q2, kv, z, xbuf);

    // Block 2: gated conv state path
    ln_kernel<false><<<BLn, 128>>>(xbuf, g2, b2, spin);
    ln_kernel<false><<<BLn, 128>>>(spin, spn_g, spn_b, hb);
    im2col_kernel<<<(BLn * 384) / 256, 256>>>(hb, im);
    gemm_mma<0><<<dim3(1024 / 128, BLn / 128), 256, GSM>>>(im, wtT, sp_cb, nullptr, qk, BLn, 1024, 3 * Cn);
    gate_kernel<<<(BLn * 128) / 256, 256>>>(qk, spin, xbuf);

    // Block 3: FFN
    ln_kernel<true><<<BLn, 128>>>(xbuf, g3, b3, ln);
    gemm_mma<1><<<dim3(FFn / 128, BLn / 128), 256, GSM>>>(ln, w1T, bb1, nullptr, ffn, BLn, FFn, Cn);
    gemm_mma<2><<<dim3(512 / 128, BLn / 128), 256, GSM>>>(ffn, w2T, bb2, xbuf, out, BLn, 512, FFn);
}

// round 4
// speedup vs baseline: 3.9477x; 1.7594x over previous
#include <cuda_runtime.h>
#include <cuda_fp16.h>
#include <math.h>
#include <stdint.h>

#define Bn 8
#define Ln 2048
#define Cn 512
#define Hn 8
#define Dn 64
#define FFn 2048
#define BLn (Bn*Ln)          /* 16384 */
#define BHn (Bn*Hn)          /* 64    */
#define BHLn (BHn*Ln)        /* 131072*/
#define KVCHUNKS 8

// ---------------- scratch (static device globals; no allocation) ----------------
static __device__ __align__(16) float  g_xbuf[BLn*Cn];
static __device__ __align__(16) __half g_lnh[BLn*Cn];
static __device__ __align__(16) float  g_qk[BLn*2*Cn];     // qk out; reused as conv output
static __device__ __align__(16) float  g_v[BLn*Cn];
static __device__ __align__(16) float  g_q2[BHLn*Dn];
static __device__ __align__(16) float  g_k2[BHLn*Dn];
static __device__ __align__(16) float  g_kmean[BHn*Dn];
static __device__ __align__(16) float  g_kv[BHn*Dn*Dn];
static __device__ __align__(16) float  g_kvpart[KVCHUNKS*BHn*Dn*Dn];
static __device__ __align__(16) float  g_z[BHLn];
static __device__ __align__(16) float  g_spin[BLn*Cn];
static __device__ __align__(16) float  g_h[BLn*Cn];
static __device__ __align__(16) __half g_im2h[BLn*3*Cn];
static __device__ __align__(16) __half g_ffnh[(long)BLn*FFn];
// transposed (N-major) half weights: B^T [N,K] row-major
static __device__ __align__(16) __half g_qkTh[1024*512];
static __device__ __align__(16) __half g_vTh[512*512];
static __device__ __align__(16) __half g_w1Th[2048*512];
static __device__ __align__(16) __half g_w2Th[512*2048];
static __device__ __align__(16) __half g_wtTh[1024*1536];

// ---------------- PTX helpers ----------------
__device__ __forceinline__ uint32_t smem_u32(const void* p) {
    uint32_t a;
    asm("{ .reg .u64 t; cvta.to.shared.u64 t, %1; cvt.u32.u64 %0, t; }" : "=r"(a) : "l"(p));
    return a;
}
__device__ __forceinline__ void cpasync16(uint32_t saddr, const void* g) {
    asm volatile("cp.async.cg.shared.global [%0], [%1], 16;" :: "r"(saddr), "l"(g) : "memory");
}
#define CP_COMMIT() asm volatile("cp.async.commit_group;" ::: "memory")
#define CP_WAIT1()  asm volatile("cp.async.wait_group 1;" ::: "memory")

__device__ __forceinline__ void ldsm4(uint32_t* r, uint32_t addr) {
    asm volatile("ldmatrix.sync.aligned.m8n8.x4.shared.b16 {%0,%1,%2,%3}, [%4];"
        : "=r"(r[0]), "=r"(r[1]), "=r"(r[2]), "=r"(r[3]) : "r"(addr));
}
// fp16 warp mma: D(16x8,f32) += A(16x16,f16) * B(16x8,f16)
__device__ __forceinline__ void mma_f16(float* c, const uint32_t* a, const uint32_t* b) {
    asm volatile(
        "mma.sync.aligned.m16n8k16.row.col.f32.f16.f16.f32 "
        "{%0,%1,%2,%3}, {%4,%5,%6,%7}, {%8,%9}, {%0,%1,%2,%3};"
        : "+f"(c[0]), "+f"(c[1]), "+f"(c[2]), "+f"(c[3])
        : "r"(a[0]), "r"(a[1]), "r"(a[2]), "r"(a[3]), "r"(b[0]), "r"(b[1]));
}

// ---------------- small helpers ----------------
__device__ __forceinline__ float elu1(float x) { return x > 0.0f ? x + 1.0f : expf(x); }
__device__ __forceinline__ uint32_t swz(uint32_t r) { return (r ^ (r >> 2)) & 3u; }

// ---------------- LayerNorm (float out) ----------------
__global__ void ln_f_kernel(const float* __restrict__ in, const float* __restrict__ gam,
                            const float* __restrict__ bet, float* __restrict__ out) {
    int row = blockIdx.x;
    int t = threadIdx.x;                 // 0..127
    const float4 v = ((const float4*)(in + (long)row * Cn))[t];
    float s  = v.x + v.y + v.z + v.w;
    float sq = v.x*v.x + v.y*v.y + v.z*v.z + v.w*v.w;
    #pragma unroll
    for (int o = 16; o; o >>= 1) {
        s  += __shfl_xor_sync(0xFFFFFFFFu, s,  o);
        sq += __shfl_xor_sync(0xFFFFFFFFu, sq, o);
    }
    __shared__ float ss[4], ssq[4];
    if ((t & 31) == 0) { ss[t >> 5] = s; ssq[t >> 5] = sq; }
    __syncthreads();
    s  = ss[0] + ss[1] + ss[2] + ss[3];
    sq = ssq[0] + ssq[1] + ssq[2] + ssq[3];
    float mu   = s * (1.0f / Cn);
    float var  = sq * (1.0f / Cn) - mu * mu;
    float rstd = rsqrtf(var + 1e-5f);
    float4 g4 = ((const float4*)gam)[t];
    float4 b4 = ((const float4*)bet)[t];
    float4 o4;
    o4.x = (v.x - mu) * rstd * g4.x + b4.x;
    o4.y = (v.y - mu) * rstd * g4.y + b4.y;
    o4.z = (v.z - mu) * rstd * g4.z + b4.z;
    o4.w = (v.w - mu) * rstd * g4.w + b4.w;
    ((float4*)(out + (long)row * Cn))[t] = o4;
}

// ---------------- LayerNorm (half out) ----------------
__global__ void ln_h_kernel(const float* __restrict__ in, const float* __restrict__ gam,
                            const float* __restrict__ bet, __half* __restrict__ out) {
    int row = blockIdx.x;
    int t = threadIdx.x;
    const float4 v = ((const float4*)(in + (long)row * Cn))[t];
    float s  = v.x + v.y + v.z + v.w;
    float sq = v.x*v.x + v.y*v.y + v.z*v.z + v.w*v.w;
    #pragma unroll
    for (int o = 16; o; o >>= 1) {
        s  += __shfl_xor_sync(0xFFFFFFFFu, s,  o);
        sq += __shfl_xor_sync(0xFFFFFFFFu, sq, o);
    }
    __shared__ float ss[4], ssq[4];
    if ((t & 31) == 0) { ss[t >> 5] = s; ssq[t >> 5] = sq; }
    __syncthreads();
    s  = ss[0] + ss[1] + ss[2] + ss[3];
    sq = ssq[0] + ssq[1] + ssq[2] + ssq[3];
    float mu   = s * (1.0f / Cn);
    float var  = sq * (1.0f / Cn) - mu * mu;
    float rstd = rsqrtf(var + 1e-5f);
    float4 g4 = ((const float4*)gam)[t];
    float4 b4 = ((const float4*)bet)[t];
    __half2 h0 = __floats2half2_rn((v.x - mu) * rstd * g4.x + b4.x,
                                   (v.y - mu) * rstd * g4.y + b4.y);
    __half2 h1 = __floats2half2_rn((v.z - mu) * rstd * g4.z + b4.z,
                                   (v.w - mu) * rstd * g4.w + b4.w);
    __half2* o = (__half2*)(out + (long)row * Cn);
    o[t * 2]     = h0;
    o[t * 2 + 1] = h1;
}

// ---------------- qk post: elu+1 then LePE ----------------
__global__ void qk_post_kernel(const float* __restrict__ qk,
                               const float* __restrict__ lw, const float* __restrict__ lb,
                               float* __restrict__ q2, float* __restrict__ k2) {
    int idx = blockIdx.x * blockDim.x + threadIdx.x;          // over BHLn*Dn
    int d  = idx & 63;
    int l  = (idx >> 6) & (Ln - 1);
    int bh = idx >> 17;
    int b = bh >> 3, h = bh & 7;
    long base = (long)b * Ln * 1024 + h * 64;
    float w0 = lw[d*3+0], w1 = lw[d*3+1], w2 = lw[d*3+2], bias = lb[d];
    int flat = d * Ln + l;
    #pragma unroll
    for (int sel = 0; sel < 2; sel++) {
        const float* src = qk + base + sel * 512;
        float acc = elu1(src[(long)l * 1024 + d]) + bias;
        if (l - 1 >= 0) {
            int fi = flat - 1; acc += w0 * elu1(src[(long)(fi >> 6) * 1024 + (fi & 63)]);
        }
        {
            int fi = flat;     acc += w1 * elu1(src[(long)(fi >> 6) * 1024 + (fi & 63)]);
        }
        if (l + 1 < Ln) {
            int fi = flat + 1; acc += w2 * elu1(src[(long)(fi >> 6) * 1024 + (fi & 63)]);
        }
        (sel ? k2 : q2)[idx] = acc;
    }
}

// ---------------- k mean ----------------
__global__ void kmean_kernel(const float* __restrict__ k2, float* __restrict__ km) {
    int bh = blockIdx.x;
    int t = threadIdx.x;
    int d = t & 63, part = t >> 6;
    float s = 0.0f;
    const float* base = k2 + (long)bh * Ln * Dn;
    for (int l = part; l < Ln; l += 4) s += base[l * 64 + d];
    __shared__ float sm[4][64];
    sm[part][d] = s;
    __syncthreads();
    if (part == 0)
        km[bh * 64 + d] = (sm[0][d] + sm[1][d] + sm[2][d] + sm[3][d]) * (1.0f / Ln);
}

// ---------------- z ----------------
__global__ void z_kernel(const float* __restrict__ q2, const float* __restrict__ km,
                         float* __restrict__ z) {
    int row  = blockIdx.x * 8 + (threadIdx.x >> 5);
    int lane = threadIdx.x & 31;
    int bh = row >> 11;
    float a = q2[(long)row * 64 + lane]      * km[bh * 64 + lane]
            + q2[(long)row * 64 + 32 + lane] * km[bh * 64 + 32 + lane];
    #pragma unroll
    for (int o = 16; o; o >>= 1) a += __shfl_xor_sync(0xFFFFFFFFu, a, o);
    if (lane == 0) z[row] = 1.0f / (a + 1e-6f);
}

// ---------------- kv partials ----------------
__global__ void kv_kernel(const float* __restrict__ k2, const float* __restrict__ v,
                          float* __restrict__ part) {
    int bh = blockIdx.x, chunk = blockIdx.y;
    int b = bh >> 3, h = bh & 7;
    __shared__ float ks[32][64];
    __shared__ float vs[32][64];
    int t = threadIdx.x;
    int e0 = (t & 15) * 4, d0 = (t >> 4) * 4;
    float acc[4][4] = {};
    int lc = Ln / KVCHUNKS;
    for (int l0 = chunk * lc; l0 < chunk * lc + lc; l0 += 32) {
        #pragma unroll
        for (int i = 0; i < 2; i++) {
            int idx = t + i * 256;
            int r = idx >> 4, c4 = (idx & 15) * 4;
            int l = l0 + r;
            *(float4*)&ks[r][c4] = *(const float4*)&k2[((long)bh * Ln + l) * 64 + c4];
            *(float4*)&vs[r][c4] = *(const float4*)&v[((long)(b * Ln + l)) * Cn + h * 64 + c4];
        }
        __syncthreads();
        #pragma unroll
        for (int l = 0; l < 32; l++) {
            float4 kr = *(const float4*)&ks[l][d0];
            float4 vr = *(const float4*)&vs[l][e0];
            float k_[4] = {kr.x, kr.y, kr.z, kr.w};
            float v_[4] = {vr.x, vr.y, vr.z, vr.w};
            #pragma unroll
            for (int i = 0; i < 4; i++)
                #pragma unroll
                for (int j = 0; j < 4; j++)
                    acc[i][j] += k_[i] * v_[j];
        }
        __syncthreads();
    }
    float* dst = part + ((long)chunk * BHn + bh) * (Dn * Dn);
    #pragma unroll
    for (int i = 0; i < 4; i++)
        #pragma unroll
        for (int j = 0; j < 4; j++)
            dst[(d0 + i) * 64 + e0 + j] = acc[i][j];
}

__global__ void kv_reduce_kernel(const float* __restrict__ part, float* __restrict__ kv) {
    int i = blockIdx.x * blockDim.x + threadIdx.x;
    float s = 0.0f;
    #pragma unroll
    for (int c = 0; c < KVCHUNKS; c++) s += part[(long)c * (BHn * Dn * Dn) + i];
    kv[i] = s * (1.0f / Ln);
}

// ---------------- attention output: xbuf = x + q2@kv * z ----------------
__global__ void attn_out_kernel(const float* __restrict__ q2, const float* __restrict__ kv,
                                const float* __restrict__ z, const float* __restrict__ x,
                                float* __restrict__ xbuf) {
    int bh = blockIdx.x, b = bh >> 3, h = bh & 7;
    int lbase = blockIdx.y * 32;
    __shared__ float kvs[64][64];
    __shared__ float qs[16][64];
    int t = threadIdx.x;
    #pragma unroll
    for (int i = 0; i < 4; i++) {
        int idx = t + i * 256;
        ((float4*)kvs)[idx] = ((const float4*)(kv + (long)bh * 4096))[idx];
    }
    int g = t >> 4;
    int e0 = (t & 15) * 4;
    for (int it = 0; it < 2; it++) {
        __syncthreads();
        int rbase = lbase + it * 16;
        #pragma unroll
        for (int i = 0; i < 4; i++) {
            int idx = t + i * 256;
            int r = idx >> 6, c = idx & 63;
            qs[r][c] = q2[((long)bh * Ln + rbase + r) * 64 + c];
        }
        __syncthreads();
        int l = rbase + g;
        float4 acc = {0.f, 0.f, 0.f, 0.f};
        #pragma unroll
        for (int d = 0; d < 64; d++) {
            float qd = qs[g][d];
            float4 kvv = *(const float4*)&kvs[d][e0];
            acc.x += qd * kvv.x; acc.y += qd * kvv.y;
            acc.z += qd * kvv.z; acc.w += qd * kvv.w;
        }
        float zz = z[(long)bh * Ln + l];
        long off = ((long)(b * Ln + l)) * Cn + h * 64 + e0;
        float4 cur = *(const float4*)&x[off];
        cur.x += acc.x * zz; cur.y += acc.y * zz;
        cur.z += acc.z * zz; cur.w += acc.w * zz;
        *(float4*)&xbuf[off] = cur;
    }
}

// ---------------- weight transposes -> half ----------------
// src [K, N] row-major -> dst [N, K] row-major half
__global__ void transpose_h_kernel(const float* __restrict__ src, __half* __restrict__ dst,
                                   int K, int N) {
    long idx = (long)blockIdx.x * blockDim.x + threadIdx.x;
    if (idx >= (long)K * N) return;
    int k = (int)(idx % K);
    int n = (int)(idx / K);
    dst[idx] = __float2half_rn(src[(long)k * N + n]);
}

// conv weight: BT[co][kk=k*512+ci] = sp_cw[co*1536 + ci*3 + k]
__global__ void wtT_kernel(const float* __restrict__ w, __half* __restrict__ wtT) {
    long idx = (long)blockIdx.x * blockDim.x + threadIdx.x;   // 1024*1536
    if (idx >= 1024L * 1536) return;
    int r  = (int)(idx % 1536);
    int co = (int)(idx / 1536);
    int k  = r >> 9;
    int ci = r & 511;
    wtT[idx] = __float2half_rn(w[co * 1536 + ci * 3 + k]);
}

// ---------------- im2col -> half ----------------
__global__ void im2col_kernel(const float* __restrict__ h, __half* __restrict__ im) {
    long idx = (long)blockIdx.x * blockDim.x + threadIdx.x;   // BLn*384 slots of 4
    int col4 = (int)(idx % 384);
    long row = idx / 384;
    int k   = col4 / 128;
    int ci4 = col4 % 128;
    int ll = (int)(row & (Ln - 1));
    int j = ll + k - 1;
    float4 vv = {0.f, 0.f, 0.f, 0.f};
    if (j >= 0 && j < Ln) vv = ((const float4*)(h + (row + k - 1) * Cn))[ci4];
    __half2* o = (__half2*)(im + row * (3 * Cn));
    o[col4 * 2]     = __floats2half2_rn(vv.x, vv.y);
    o[col4 * 2 + 1] = __floats2half2_rn(vv.z, vv.w);
}

// ---------------- gate ----------------
__global__ void gate_kernel(const float* __restrict__ c, const float* __restrict__ spin,
                            float* __restrict__ xbuf) {
    long idx = (long)blockIdx.x * blockDim.x + threadIdx.x;
    int c4 = (int)(idx & 127);
    long row = idx >> 7;
    float4 vv = ((const float4*)(c + row * 1024))[c4];
    float4 gg = ((const float4*)(c + row * 1024 + 512))[c4];
    float4 sp = ((const float4*)(spin + row * Cn))[c4];
    float4 x  = ((float4*)(xbuf + row * Cn))[c4];
    x.x += sp.x + vv.x / (1.0f + expf(-gg.x));
    x.y += sp.y + vv.y / (1.0f + expf(-gg.y));
    x.z += sp.z + vv.z / (1.0f + expf(-gg.z));
    x.w += sp.w + vv.w / (1.0f + expf(-gg.w));
    ((float4*)(xbuf + row * Cn))[c4] = x;
}

// ================= fp16 mma.sync GEMM =================
// C[M,N] = A[M,K] @ Bt[N,K]^T, A/Bt half.  CTA tile 128x128, K-chunk 32, 3-stage cp.async.
// 8 warps: warp grid 2(m) x 4(n), warp tile 64x32 = 4x4 m16n8k16 atoms, 2 k-blocks/chunk.
// smem stage = A 8KB + B 8KB; row = 32 halfs (64B), phys chunk16 = c ^ ((r^(r>>2))&3).
// EPI: 0 = bias (float out); 1 = bias + exact GELU (half out); 2 = bias + residual (float out).
#define GSM (3 * 16384)

template<int EPI>
__global__ void __launch_bounds__(256, 2)
gemm_h(const __half* __restrict__ A, const __half* __restrict__ Bt,
       const float* __restrict__ bias, const float* __restrict__ res,
       void* __restrict__ Cv, int M, int N, int K) {
    extern __shared__ char smraw[];
    uint32_t sb = smem_u32(smraw);
    int t = threadIdx.x, wid = t >> 5, lane = t & 31;
    int g = lane >> 2, tig = lane & 3;
    int bm = blockIdx.y * 128, bn = blockIdx.x * 128;
    int wm = (wid >> 2) * 64, wn = (wid & 3) * 32;

    // ---- cp.async slots: 2 chunks A + 2 chunks B per thread per stage ----
    const __half* aG[2]; const __half* bG[2]; uint32_t offA[2], offB[2];
    #pragma unroll
    for (int i = 0; i < 2; i++) {
        int idx = t + i * 256;                 // 0..511
        int r = idx >> 2;                      // row 0..127
        int c = idx & 3;                       // 16B chunk in row
        uint32_t off = (uint32_t)r * 64 + ((c ^ swz(r)) << 4);
        offA[i] = off;
        offB[i] = off + 8192;
        aG[i] = A + (long)(bm + r) * K + c * 8;
        bG[i] = Bt + (long)(bn + r) * K + c * 8;
    }

    // ---- ldmatrix per-thread address components ----
    // A(mt, kb): lanes 0-15 -> rows m0..m0+15 (chunk base), 16-31 -> same rows chunk+1
    uint32_t aRow[4], aSw[4];
    #pragma unroll
    for (int mt = 0; mt < 4; mt++) {
        uint32_t m = wm + mt * 16 + (lane & 15);
        aRow[mt] = m * 64;
        aSw[mt] = swz(m);
    }
    uint32_t cHiA = lane >> 4;
    // B(ntp, kb): lanes {0-7,16-23} rows n0+(0..7)/(8..15) chunk base; {8-15,24-31} chunk+1
    uint32_t bRow[2], bSw[2];
    #pragma unroll
    for (int np = 0; np < 2; np++) {
        uint32_t n = wn + np * 16 + ((lane >> 4) << 3) + (lane & 7);
        bRow[np] = n * 64 + 8192;
        bSw[np] = swz(n);
    }
    uint32_t cHiB = (lane >> 3) & 1;

    int nk = K >> 5;   // K-chunks of 32

    // prologue: stages 0,1
    #pragma unroll
    for (int s = 0; s < 2; s++) {
        uint32_t stb = sb + s * 16384;
        #pragma unroll
        for (int i = 0; i < 2; i++) {
            cpasync16(stb + offA[i], aG[i] + s * 32);
            cpasync16(stb + offB[i], bG[i] + s * 32);
        }
        CP_COMMIT();
    }
    CP_WAIT1();
    __syncthreads();

    float acc[4][4][4] = {};

    for (int kt = 0; kt < nk; kt++) {
        if (kt + 2 < nk) {
            uint32_t stb = sb + ((kt + 2) % 3) * 16384;
            #pragma unroll
            for (int i = 0; i < 2; i++) {
                cpasync16(stb + offA[i], aG[i] + (long)(kt + 2) * 32);
                cpasync16(stb + offB[i], bG[i] + (long)(kt + 2) * 32);
            }
        }
        CP_COMMIT();

        uint32_t stb = sb + (kt % 3) * 16384;
        #pragma unroll
        for (int kb = 0; kb < 2; kb++) {
            uint32_t a[4][4], b[4][2];
            #pragma unroll
            for (int mt = 0; mt < 4; mt++) {
                uint32_t addr = stb + aRow[mt] + ((((uint32_t)(2 * kb) | cHiA) ^ aSw[mt]) << 4);
                ldsm4(a[mt], addr);
            }
            #pragma unroll
            for (int np = 0; np < 2; np++) {
                uint32_t bb[4];
                uint32_t addr = stb + bRow[np] + ((((uint32_t)(2 * kb) | cHiB) ^ bSw[np]) << 4);
                ldsm4(bb, addr);
                b[2*np][0] = bb[0]; b[2*np][1] = bb[1];
                b[2*np+1][0] = bb[2]; b[2*np+1][1] = bb[3];
            }
            #pragma unroll
            for (int mt = 0; mt < 4; mt++)
                #pragma unroll
                for (int nt = 0; nt < 4; nt++)
                    mma_f16(acc[mt][nt], a[mt], b[nt]);
        }

        CP_WAIT1();
        __syncthreads();
    }

    // ---- epilogue ----
    #pragma unroll
    for (int mt = 0; mt < 4; mt++) {
        int row = bm + wm + mt * 16 + g;
        #pragma unroll
        for (int nt = 0; nt < 4; nt++) {
            int col = bn + wn + nt * 8 + tig * 2;
            float b0 = bias[col], b1 = bias[col + 1];
            float v00 = acc[mt][nt][0] + b0;
            float v01 = acc[mt][nt][1] + b1;
            float v10 = acc[mt][nt][2] + b0;
            float v11 = acc[mt][nt][3] + b1;
            if (EPI == 1) {
                v00 = 0.5f * v00 * (1.0f + erff(v00 * 0.70710678118654752f));
                v01 = 0.5f * v01 * (1.0f + erff(v01 * 0.70710678118654752f));
                v10 = 0.5f * v10 * (1.0f + erff(v10 * 0.70710678118654752f));
                v11 = 0.5f * v11 * (1.0f + erff(v11 * 0.70710678118654752f));
                __half2* C = (__half2*)Cv;
                C[((long)row * N + col) >> 1]       = __floats2half2_rn(v00, v01);
                C[((long)(row + 8) * N + col) >> 1] = __floats2half2_rn(v10, v11);
            } else {
                if (EPI == 2) {
                    const float* r0 = res + (long)row * N + col;
                    const float* r1 = res + (long)(row + 8) * N + col;
                    v00 += r0[0]; v01 += r0[1];
                    v10 += r1[0]; v11 += r1[1];
                }
                float* C = (float*)Cv;
                float2 p0 = {v00, v01}, p1 = {v10, v11};
                *(float2*)(C + (long)row * N + col)       = p0;
                *(float2*)(C + (long)(row + 8) * N + col) = p1;
            }
        }
    }
}

// ---------------- host launcher ----------------
extern "C" void kernel_launch(void* const* d_in, const int* in_sizes, int n_in,
                              void* d_out, int out_size) {
    const float* x      = (const float*)d_in[0];
    const float* g1     = (const float*)d_in[1];
    const float* b1     = (const float*)d_in[2];
    const float* qk_w   = (const float*)d_in[3];
    const float* qk_b   = (const float*)d_in[4];
    const float* v_w    = (const float*)d_in[5];
    const float* v_b    = (const float*)d_in[6];
    const float* lepe_w = (const float*)d_in[7];
    const float* lepe_b = (const float*)d_in[8];
    const float* g2     = (const float*)d_in[9];
    const float* b2     = (const float*)d_in[10];
    const float* spn_g  = (const float*)d_in[11];
    const float* spn_b  = (const float*)d_in[12];
    const float* sp_cw  = (const float*)d_in[13];
    const float* sp_cb  = (const float*)d_in[14];
    const float* g3     = (const float*)d_in[15];
    const float* b3     = (const float*)d_in[16];
    const float* w1     = (const float*)d_in[17];
    const float* bb1    = (const float*)d_in[18];
    const float* w2     = (const float*)d_in[19];
    const float* bb2    = (const float*)d_in[20];
    float* out = (float*)d_out;

    float *xbuf, *qk, *v, *q2, *k2, *km, *kv, *kvpart, *z, *spin, *hb;
    __half *lnh, *im2h, *ffnh, *qkTh, *vTh, *w1Th, *w2Th, *wtTh;
    cudaGetSymbolAddress((void**)&xbuf,   g_xbuf);
    cudaGetSymbolAddress((void**)&lnh,    g_lnh);
    cudaGetSymbolAddress((void**)&qk,     g_qk);
    cudaGetSymbolAddress((void**)&v,      g_v);
    cudaGetSymbolAddress((void**)&q2,     g_q2);
    cudaGetSymbolAddress((void**)&k2,     g_k2);
    cudaGetSymbolAddress((void**)&km,     g_kmean);
    cudaGetSymbolAddress((void**)&kv,     g_kv);
    cudaGetSymbolAddress((void**)&kvpart, g_kvpart);
    cudaGetSymbolAddress((void**)&z,      g_z);
    cudaGetSymbolAddress((void**)&spin,   g_spin);
    cudaGetSymbolAddress((void**)&hb,     g_h);
    cudaGetSymbolAddress((void**)&im2h,   g_im2h);
    cudaGetSymbolAddress((void**)&ffnh,   g_ffnh);
    cudaGetSymbolAddress((void**)&qkTh,   g_qkTh);
    cudaGetSymbolAddress((void**)&vTh,    g_vTh);
    cudaGetSymbolAddress((void**)&w1Th,   g_w1Th);
    cudaGetSymbolAddress((void**)&w2Th,   g_w2Th);
    cudaGetSymbolAddress((void**)&wtTh,   g_wtTh);

    cudaFuncSetAttribute(gemm_h<0>, cudaFuncAttributeMaxDynamicSharedMemorySize, GSM);
    cudaFuncSetAttribute(gemm_h<1>, cudaFuncAttributeMaxDynamicSharedMemorySize, GSM);
    cudaFuncSetAttribute(gemm_h<2>, cudaFuncAttributeMaxDynamicSharedMemorySize, GSM);

    // weight transposes (half)
    transpose_h_kernel<<<(512 * 1024 + 255) / 256, 256>>>(qk_w, qkTh, 512, 1024);
    transpose_h_kernel<<<(512 * 512 + 255) / 256, 256>>>(v_w, vTh, 512, 512);
    transpose_h_kernel<<<(512 * 2048 + 255) / 256, 256>>>(w1, w1Th, 512, 2048);
    transpose_h_kernel<<<(2048 * 512 + 255) / 256, 256>>>(w2, w2Th, 2048, 512);
    wtT_kernel<<<(1024 * 1536 + 255) / 256, 256>>>(sp_cw, wtTh);

    // Block 1: xbuf = x + attn(LN1(x))
    ln_h_kernel<<<BLn, 128>>>(x, g1, b1, lnh);
    gemm_h<0><<<dim3(1024 / 128, BLn / 128), 256, GSM>>>(lnh, qkTh, qk_b, nullptr, qk, BLn, 1024, Cn);
    gemm_h<0><<<dim3(512 / 128, BLn / 128), 256, GSM>>>(lnh, vTh, v_b, nullptr, v, BLn, 512, Cn);
    qk_post_kernel<<<(BHLn * Dn) / 256, 256>>>(qk, lepe_w, lepe_b, q2, k2);
    kmean_kernel<<<BHn, 256>>>(k2, km);
    z_kernel<<<BHLn / 8, 256>>>(q2, km, z);
    kv_kernel<<<dim3(BHn, KVCHUNKS), 256>>>(k2, v, kvpart);
    kv_reduce_kernel<<<(BHn * Dn * Dn) / 256, 256>>>(kvpart, kv);
    attn_out_kernel<<<dim3(BHn, Ln / 32), 256>>>(q2, kv, z, x, xbuf);

    // Block 2: gated conv state path
    ln_f_kernel<<<BLn, 128>>>(xbuf, g2, b2, spin);
    ln_f_kernel<<<BLn, 128>>>(spin, spn_g, spn_b, hb);
    im2col_kernel<<<(BLn * 384) / 256, 256>>>(hb, im2h);
    gemm_h<0><<<dim3(1024 / 128, BLn / 128), 256, GSM>>>(im2h, wtTh, sp_cb, nullptr, qk, BLn, 1024, 3 * Cn);
    gate_kernel<<<(BLn * 128) / 256, 256>>>(qk, spin, xbuf);

    // Block 3: FFN
    ln_h_kernel<<<BLn, 128>>>(xbuf, g3, b3, lnh);
    gemm_h<1><<<dim3(FFn / 128, BLn / 128), 256, GSM>>>(lnh, w1Th, bb1, nullptr, ffnh, BLn, FFn, Cn);
    gemm_h<2><<<dim3(512 / 128, BLn / 128), 256, GSM>>>(ffnh, w2Th, bb2, xbuf, out, BLn, 512, FFn);
}